// round 10
// baseline (speedup 1.0000x reference)
#include <cuda_runtime.h>
#include <cstdint>

#define BB 20
#define LL 20
#define VV 100000
#define NP (BB * LL * LL)     // 8000 gathered elements
#define CSZ 8                 // cluster size
#define PROD_CNT 1143         // ceil(8000/7): elements per producer CTA

#define PAD_LO 352            // floats; covers tile-DP inactive-lane offsets
#define PAD_HI 352

// ---------------------------------------------------------------------------
// One 8-CTA cluster, single launch.
//   Ranks 1..7: gather ~1143 scattered elements each and write them directly
//     into rank 0's shared memory via mapa + st.shared::cluster, then
//     cluster-arrive (release) and wait.
//   Rank 0: cluster-arrive immediately, does all P-independent prework
//     (labels, ballots, constants) overlapping the producers, cluster-waits
//     (acquire), then runs the DP.
//   Fast-path DP (all masks set -- always for this data): 2x2-tile
//     anti-diagonal wavefront, 19 steps. 10 warps; warp w = batches
//     {2w, 2w+1} in 16-lane segments; lane c owns columns 2c+1, 2c+2 and
//     processes row pair (2r+1, 2r+2) at step t = r + c. Two parallel
//     segmented shfls/step carry the neighbor's two bottom-column cells;
//     the third needed value (dp[2r][2c]) is the previous step's shfl (dlag).
//   General path: original 29-step masked wavefront.
// ---------------------------------------------------------------------------
__global__ void __cluster_dims__(CSZ, 1, 1) __launch_bounds__(320)
calcs_cluster_kernel(
    const float* __restrict__ topic_prob,
    const int*   __restrict__ hard_label,
    float*       __restrict__ out)
{
    __shared__ float4 s_buf4[(PAD_LO + NP + PAD_HI) / 4];
    __shared__ float  s_loss[BB];
    float* s_P = ((float*)s_buf4) + PAD_LO;

    const int tid = threadIdx.x;
    unsigned int rank;
    asm("mov.u32 %0, %%cluster_ctarank;" : "=r"(rank));

    if (rank != 0) {
        // ---------------- producers ----------------
        unsigned int laddr;
        asm("{ .reg .u64 t; cvta.to.shared.u64 t, %1; cvt.u32.u64 %0, t; }"
            : "=r"(laddr) : "l"((void*)s_P));
        unsigned int raddr0;
        asm("mapa.shared::cluster.u32 %0, %1, 0;" : "=r"(raddr0) : "r"(laddr));

        const int start = ((int)rank - 1) * PROD_CNT;
        #pragma unroll
        for (int it = 0; it < 4; ++it) {
            const int rel = tid + it * 320;
            const int i = start + rel;
            if (rel < PROD_CNT && i < NP) {
                const int b = i / (LL * LL);
                const int j = (i / LL) % LL;
                const int k = i % LL;
                const int lab = __ldg(&hard_label[b * LL + k]);
                const int idx = lab < 0 ? 0 : (lab > (VV - 1) ? (VV - 1) : lab);
                const float v = __ldg(&topic_prob[(size_t)(b * LL + j) * VV + idx]);
                asm volatile("st.shared::cluster.f32 [%0], %1;"
                             :: "r"(raddr0 + 4u * (unsigned int)i), "f"(v) : "memory");
            }
        }
        asm volatile("barrier.cluster.arrive.aligned;" ::: "memory");  // release
        asm volatile("barrier.cluster.wait.aligned;" ::: "memory");
        return;
    }

    // ---------------- rank 0 ----------------
    asm volatile("barrier.cluster.arrive.aligned;" ::: "memory");  // arrive early

    const int warp = tid >> 5;
    const int lane = tid & 31;
    const int sub  = lane & 15;
    const int half = lane >> 4;

    // prework overlapping producers (nothing touches s_P data yet)
    const int b0 = 2 * warp, b1 = 2 * warp + 1;
    const int l0 = (lane < LL) ? __ldg(&hard_label[b0 * LL + lane]) : -1;
    const unsigned bal0 = __ballot_sync(0xFFFFFFFFu, (lane < LL) && (l0 >= 0));
    const int l1 = (lane < LL) ? __ldg(&hard_label[b1 * LL + lane]) : -1;
    const unsigned bal1 = __ballot_sync(0xFFFFFFFFu, (lane < LL) && (l1 >= 0));

    const unsigned bal = half ? bal1 : bal0;
    const int len = __popc(bal & 0xFFFFFu);
    const int b   = half ? b1 : b0;
    const int c   = sub;

    // wait for producers' DSMEM stores (acquire)
    asm volatile("barrier.cluster.wait.aligned;" ::: "memory");

    if (bal0 == 0xFFFFFu && bal1 == 0xFFFFFu) {
        // ---- fast path: 2x2-tile wavefront, 19 steps, len == 20 ----
        // lane c, step t: row pair r = t - c (0..9), rows j1=2r+1, j2=2r+2,
        // cols kA=2c+1, kB=2c+2. P addr for (j1,kA): base + 40t - 38c.
        const float* pbase = s_P + b * (LL * LL) - 38 * c;
        float prevA = 0.0f, prevB = 0.0f;   // dp[2r][kA], dp[2r][kB]
        float vB1 = 0.0f, vB2 = 0.0f;       // this lane's col-kB pair values
        float dlag = 0.0f;                  // neighbor dp[2r][2c]

        #pragma unroll
        for (int t = 0; t <= 18; ++t) {
            float nB1 = __shfl_up_sync(0xFFFFFFFFu, vB1, 1, 16); // dp[2r+1][2c]
            float nB2 = __shfl_up_sync(0xFFFFFFFFu, vB2, 1, 16); // dp[2r+2][2c]
            if (sub == 0) { nB1 = 0.0f; nB2 = 0.0f; }

            const int  r   = t - c;
            const bool act = (c < 10) && (r >= 0) && (r <= 9);

            const float2 p1 = *(const float2*)(pbase + 40 * t);      // (j1,kA),(j1,kB)
            const float2 p2 = *(const float2*)(pbase + 40 * t + LL); // (j2,kA),(j2,kB)

            // cell (j1,kA): left=nB1, up=prevA, diag=dlag
            const float Ma1 = fmaxf(nB1, prevA);
            const float a1  = fmaf(p1.x, dlag + 1.0f - Ma1, Ma1);
            // cell (j1,kB): left=a1, up=prevB, diag=prevA
            const float Mb1 = fmaxf(a1, prevB);
            const float b1v = fmaf(p1.y, prevA + 1.0f - Mb1, Mb1);
            // cell (j2,kA): left=nB2, up=a1, diag=nB1
            const float Ma2 = fmaxf(nB2, a1);
            const float a2  = fmaf(p2.x, nB1 + 1.0f - Ma2, Ma2);
            // cell (j2,kB): left=a2, up=b1v, diag=a1
            const float Mb2 = fmaxf(a2, b1v);
            const float b2v = fmaf(p2.y, a1 + 1.0f - Mb2, Mb2);

            if (act) {
                vB1 = b1v; vB2 = b2v;
                prevA = a2; prevB = b2v;
            }
            dlag = nB2;   // next step's diag source (unconditional)
        }

        if (sub == 9)                      // lane owning column 20: dp[20][20]
            s_loss[b] = -logf(prevB * (1.0f / 20.0f));
    } else {
        // ---- general path: original 29-step masked wavefront ----
        const int  base  = b * (LL * LL) - 18 * c - LL;
        const bool capA  = (2 * c + 1 == len);
        const bool capB  = (2 * c + 2 == len);
        const bool valid = (c < 10);
        const unsigned bitA = (bal >> (2 * c)) & 1u;
        const unsigned bitB = (bal >> (2 * c + 1)) & 1u;

        float prevA = 0.0f, prevB = 0.0f, dleft = 0.0f, result = 0.0f;

        #pragma unroll
        for (int t = 1; t <= LL + 9; ++t) {
            float left = __shfl_up_sync(0xFFFFFFFFu, prevB, 1, 16);
            if (sub == 0) left = 0.0f;
            const float diag = dleft;
            dleft = left;

            const int  j   = t - c;
            const bool act = valid && (j >= 1) && (j <= LL);
            const int  js  = (j < 1) ? 1 : (j > LL ? LL : j);
            const unsigned mj = (bal >> (js - 1)) & 1u;

            const float2 p2 = *(const float2*)(s_P + base + t * LL);

            const float Ma = fmaxf(left, prevA);
            float vA = fmaf(p2.x, diag + 1.0f - Ma, Ma);
            vA = (mj & bitA) ? vA : 0.0f;
            const float Mb = fmaxf(vA, prevB);
            float vB = fmaf(p2.y, prevA + 1.0f - Mb, Mb);
            vB = (mj & bitB) ? vB : 0.0f;

            if (act) {
                if (j == len) {
                    if (capA) result = vA;
                    if (capB) result = vB;
                }
                prevA = vA;
                prevB = vB;
            }
        }

        if (len > 0) {
            if ((capA || capB) && valid)
                s_loss[b] = -logf(result / (float)len);
        } else if (sub == 0) {
            s_loss[b] = -logf(0.0f / 0.0f);   // 0/0 -> nan, matches reference
        }
    }
    __syncthreads();

    if (warp == 0) {
        float v = (lane < BB) ? s_loss[lane] : 0.0f;
        #pragma unroll
        for (int off = 16; off > 0; off >>= 1)
            v += __shfl_down_sync(0xFFFFFFFFu, v, off);
        if (lane == 0) out[0] = v * (1.0f / (float)BB);
    }
}

extern "C" void kernel_launch(void* const* d_in, const int* in_sizes, int n_in,
                              void* d_out, int out_size) {
    const float* topic_prob = (const float*)d_in[0];
    const int*   hard_label = (const int*)d_in[1];
    float*       out        = (float*)d_out;
    calcs_cluster_kernel<<<CSZ, 320>>>(topic_prob, hard_label, out);
}